// round 1
// baseline (speedup 1.0000x reference)
#include <cuda_runtime.h>

#define DIM 128
#define MAX_NODES 65536

// Scratch: per-node precomputed Q[n] = (nf[n]-centroid[g]) @ [W1b | W1c], 256 floats/node.
__device__ float g_Q[MAX_NODES * 2 * DIM];
__device__ int g_idx64;  // 1 if edge_index is int64, 0 if int32

// ---------------------------------------------------------------------------
// Detect edge_index dtype: if int64, every odd 32-bit word (high half of a
// non-negative value < 2^31) is zero. If int32, odd words are node ids.
// ---------------------------------------------------------------------------
__global__ void detect_idx_kernel(const unsigned int* __restrict__ w) {
    __shared__ int s_any;
    if (threadIdx.x == 0) s_any = 0;
    __syncthreads();
    int found = 0;
    for (int i = threadIdx.x; i < 4096; i += blockDim.x)
        if (w[2 * i + 1] != 0u) found = 1;
    if (found) atomicOr(&s_any, 1);
    __syncthreads();
    if (threadIdx.x == 0) g_idx64 = (s_any == 0) ? 1 : 0;
}

// ---------------------------------------------------------------------------
// Precompute Q[n][c] for c in [0,256):
//   c <  128 : residual[n] @ W1b column c        (multiplies res_i)
//   c >= 128 : residual[n] @ W1c column (c-128)  (multiplies res_j)
// residual[n] = nf[n] - centroid[n / npg]
// Block: 256 threads, 8 nodes per block.
// ---------------------------------------------------------------------------
__global__ void precompute_kernel(const float* __restrict__ nf,
                                  const float* __restrict__ centroid,
                                  const float* __restrict__ W1,
                                  int n_nodes, int npg) {
    __shared__ float s_res[8][DIM];
    const int base = blockIdx.x * 8;
    const int t = threadIdx.x;

    for (int idx = t; idx < 8 * DIM; idx += 256) {
        int node = base + (idx >> 7);
        int d = idx & (DIM - 1);
        float v = 0.0f;
        if (node < n_nodes)
            v = nf[node * DIM + d] - centroid[(node / npg) * DIM + d];
        s_res[idx >> 7][d] = v;
    }
    __syncthreads();

    const int c = t;  // 0..255
    const float* wcol = (c < DIM) ? (W1 + DIM * DIM + c)
                                  : (W1 + 2 * DIM * DIM + (c - DIM));
    float acc[8];
#pragma unroll
    for (int k = 0; k < 8; k++) acc[k] = 0.0f;

#pragma unroll 4
    for (int d = 0; d < DIM; d++) {
        float wv = wcol[d * DIM];
#pragma unroll
        for (int k = 0; k < 8; k++) acc[k] = fmaf(wv, s_res[k][d], acc[k]);
    }

#pragma unroll
    for (int k = 0; k < 8; k++) {
        int node = base + k;
        if (node < n_nodes) g_Q[node * (2 * DIM) + c] = acc[k];
    }
}

// ---------------------------------------------------------------------------
// Edge kernel. Per edge e with src = edge_index[0][e] (node_j),
// dst = edge_index[1][e] (node_i):
//   h = relu( |nf[dst]-nf[src]| @ W1a + Q[dst][0:128] + Q[src][128:256] + b1 )
//   out[e] = h @ W2 + b2
// Block: 256 threads (8 warps). W1a (64 KB) staged in smem. Each warp handles
// 4 edges per tile with 4x4 register blocking over the 128x128 matvec.
// ---------------------------------------------------------------------------
__global__ void edge_kernel(const float* __restrict__ nf,
                            const void* __restrict__ ei,
                            const float* __restrict__ W1,
                            const float* __restrict__ b1,
                            const float* __restrict__ W2,
                            const float* __restrict__ b2,
                            float* __restrict__ out,
                            int E) {
    extern __shared__ float smem[];
    float* sW  = smem;                 // 128*128
    float* sB1 = sW + DIM * DIM;       // 128
    float* sW2 = sB1 + DIM;            // 128
    float* sA  = sW2 + DIM;            // 8 warps * 4 edges * 128

    const int t = threadIdx.x;
    for (int i = t; i < DIM * DIM / 4; i += blockDim.x)
        ((float4*)sW)[i] = ((const float4*)W1)[i];
    if (t < DIM) { sB1[t] = b1[t]; sW2[t] = W2[t]; }
    __syncthreads();

    const float bias2 = b2[0];
    const int warp = t >> 5;
    const int lane = t & 31;
    const int mode64 = g_idx64;
    const long long* ei64 = (const long long*)ei;
    const int* ei32 = (const int*)ei;
    float* aw = sA + warp * (4 * DIM);
    const int k0 = lane * 4;
    const float4 b1v = *(const float4*)(sB1 + k0);
    const float4 w2v = *(const float4*)(sW2 + k0);

    const int tiles = (E + 31) >> 5;
    for (int tile = blockIdx.x; tile < tiles; tile += gridDim.x) {
        const int e0 = tile * 32 + warp * 4;

        int src[4], dst[4];
#pragma unroll
        for (int e = 0; e < 4; e++) {
            int eid = e0 + e;
            if (eid < E) {
                if (mode64) { src[e] = (int)ei64[eid]; dst[e] = (int)ei64[E + eid]; }
                else        { src[e] = ei32[eid];      dst[e] = ei32[E + eid]; }
            } else { src[e] = 0; dst[e] = 0; }
        }

#pragma unroll
        for (int e = 0; e < 4; e++) {
            const float* pi = nf + (size_t)dst[e] * DIM;
            const float* pj = nf + (size_t)src[e] * DIM;
#pragma unroll
            for (int r = 0; r < 4; r++) {
                int d = lane + 32 * r;
                aw[e * DIM + d] = fabsf(pi[d] - pj[d]);
            }
        }
        __syncwarp();

        float4 acc[4];
#pragma unroll
        for (int e = 0; e < 4; e++) {
            const float4 qb = *(const float4*)(g_Q + (size_t)dst[e] * (2 * DIM) + k0);
            const float4 qc = *(const float4*)(g_Q + (size_t)src[e] * (2 * DIM) + DIM + k0);
            acc[e].x = qb.x + qc.x + b1v.x;
            acc[e].y = qb.y + qc.y + b1v.y;
            acc[e].z = qb.z + qc.z + b1v.z;
            acc[e].w = qb.w + qc.w + b1v.w;
        }

#pragma unroll 4
        for (int d = 0; d < DIM; d++) {
            const float4 wv = *(const float4*)(sW + d * DIM + k0);
#pragma unroll
            for (int e = 0; e < 4; e++) {
                float a = aw[e * DIM + d];
                acc[e].x = fmaf(a, wv.x, acc[e].x);
                acc[e].y = fmaf(a, wv.y, acc[e].y);
                acc[e].z = fmaf(a, wv.z, acc[e].z);
                acc[e].w = fmaf(a, wv.w, acc[e].w);
            }
        }

#pragma unroll
        for (int e = 0; e < 4; e++) {
            float s = fmaxf(acc[e].x, 0.f) * w2v.x
                    + fmaxf(acc[e].y, 0.f) * w2v.y
                    + fmaxf(acc[e].z, 0.f) * w2v.z
                    + fmaxf(acc[e].w, 0.f) * w2v.w;
#pragma unroll
            for (int off = 16; off > 0; off >>= 1)
                s += __shfl_down_sync(0xffffffffu, s, off);
            if (lane == 0) {
                int eid = e0 + e;
                if (eid < E) out[eid] = s + bias2;
            }
        }
        __syncwarp();
    }
}

// ---------------------------------------------------------------------------
// Launch. Inputs identified by element count (robust to 'bs' scalar being
// present or absent in metadata order):
//   node_features 65536*128=8388608, edge_index 1000000, centroid 2048,
//   W1 49152, b1 128 (first), W2 128 (second), b2 = last size-1 input.
// ---------------------------------------------------------------------------
extern "C" void kernel_launch(void* const* d_in, const int* in_sizes, int n_in,
                              void* d_out, int out_size) {
    const float *nf = 0, *centroid = 0, *W1 = 0, *b1 = 0, *W2 = 0, *b2 = 0;
    const void* ei = 0;
    int nf_elems = 0, cen_elems = 0;
    int last_size1 = -1;

    for (int i = 0; i < n_in; i++) {
        int s = in_sizes[i];
        if (s == 1) { last_size1 = i; continue; }
        if (s == 128) {
            if (!b1) b1 = (const float*)d_in[i];
            else     W2 = (const float*)d_in[i];
            continue;
        }
        if (s == 2048) { centroid = (const float*)d_in[i]; cen_elems = s; continue; }
        if (s == 49152) { W1 = (const float*)d_in[i]; continue; }
        if (s == 2 * out_size) { ei = d_in[i]; continue; }
        if (s > nf_elems) { nf = (const float*)d_in[i]; nf_elems = s; }
    }
    if (last_size1 >= 0) b2 = (const float*)d_in[last_size1];

    const int E = out_size;
    const int n_nodes = nf_elems / DIM;
    const int bs = cen_elems / DIM;
    const int npg = n_nodes / (bs > 0 ? bs : 1);

    detect_idx_kernel<<<1, 256>>>((const unsigned int*)ei);

    precompute_kernel<<<(n_nodes + 7) / 8, 256>>>(nf, centroid, W1, n_nodes, npg);

    const size_t shbytes = (size_t)(DIM * DIM + DIM + DIM + 8 * 4 * DIM) * sizeof(float);
    cudaFuncSetAttribute(edge_kernel, cudaFuncAttributeMaxDynamicSharedMemorySize,
                         (int)shbytes);
    edge_kernel<<<2048, 256, shbytes>>>(nf, ei, W1, b1, W2, b2, (float*)d_out, E);
}